// round 8
// baseline (speedup 1.0000x reference)
#include <cuda_runtime.h>
#include <cstdint>
#include <math.h>

#define BB 128
#define NN 1000
#define DD 196
#define KK 48
#define NC 64            // candidate columns (top-NC of x per batch row)
#define NO (DD - NC)     // 132 other columns
#define NWARPS 32
#define THREADS (NWARPS * 32)

__device__ __forceinline__ unsigned f2key(float v) {
    unsigned u = __float_as_uint(v);
    return u ^ ((unsigned)((int)u >> 31) | 0x80000000u);
}

// Exact full-width fallback: top-KK of all 196 perturbed values, d-ascending ranks.
__device__ __noinline__ void fallback_select(const float* __restrict__ row,
                                             const float* __restrict__ xb,
                                             float sigma, int* acc,
                                             int lane, unsigned lt)
{
    const unsigned FULL = 0xffffffffu;
    unsigned key[7];
#pragma unroll
    for (int j = 0; j < 7; ++j) {
        int d = j * 32 + lane;
        key[j] = (d < DD) ? f2key(fmaf(sigma, row[d], xb[d])) : 0u;
    }
    unsigned prefix = 0;
    for (int bit = 31; bit >= 0; --bit) {
        unsigned t = prefix | (1u << bit);
        int c = 0;
#pragma unroll
        for (int j = 0; j < 7; ++j) c += (key[j] >= t);
        c = __reduce_add_sync(FULL, c);
        if (c >= KK) { prefix = t; if (c == KK) break; }
    }
    int cgt = 0;
#pragma unroll
    for (int j = 0; j < 7; ++j) cgt += (key[j] > prefix);
    cgt = __reduce_add_sync(FULL, cgt);
    int rem = KK - cgt;
    int selb = 0, eqb = 0;
#pragma unroll
    for (int j = 0; j < 7; ++j) {
        bool gt = key[j] > prefix;
        bool eq = (key[j] == prefix);
        unsigned be = __ballot_sync(FULL, eq);
        bool sel = gt || (eq && (eqb + __popc(be & lt)) < rem);
        unsigned bs = __ballot_sync(FULL, sel);
        if (sel) atomicAdd(&acc[(selb + __popc(bs & lt)) * DD + (j * 32 + lane)], 1);
        eqb += __popc(be);
        selb += __popc(bs);
    }
}

__global__ __launch_bounds__(THREADS, 1)
void ptk_kernel(const float* __restrict__ x,
                const float* __restrict__ noise,
                const float* __restrict__ sigma_p,
                float* __restrict__ out)
{
    __shared__ int acc[KK * DD];   // 37632 B
    __shared__ short cidx[NC];     // candidate column ids, ascending d
    __shared__ short oidx[NO];     // other column ids, ascending d

    const int b = blockIdx.x, tid = threadIdx.x, lane = tid & 31, warp = tid >> 5;
    const unsigned lt = (1u << lane) - 1u;
    const unsigned FULL = 0xffffffffu;

    for (int i = tid; i < KK * DD; i += THREADS) acc[i] = 0;

    // ---- per-b precompute (warp 0): exact top-NC columns of x ----
    if (warp == 0) {
        unsigned key[7];
#pragma unroll
        for (int j = 0; j < 7; ++j) {
            int d = j * 32 + lane;
            key[j] = (d < DD) ? f2key(x[b * DD + d]) : 0u;
        }
        unsigned prefix = 0;
        for (int bit = 31; bit >= 0; --bit) {
            unsigned t = prefix | (1u << bit);
            int c = 0;
#pragma unroll
            for (int j = 0; j < 7; ++j) c += (key[j] >= t);
            c = __reduce_add_sync(FULL, c);
            if (c >= NC) { prefix = t; if (c == NC) break; }
        }
        int cgt = 0;
#pragma unroll
        for (int j = 0; j < 7; ++j) cgt += (key[j] > prefix);
        cgt = __reduce_add_sync(FULL, cgt);
        int rem = NC - cgt;
        int cb = 0, ob = 0, eqb = 0;
#pragma unroll
        for (int j = 0; j < 7; ++j) {
            int d = j * 32 + lane;
            bool valid = d < DD;
            bool gt = key[j] > prefix;
            bool eq = valid && (key[j] == prefix);
            unsigned be = __ballot_sync(FULL, eq);
            bool sel = gt || (eq && (eqb + __popc(be & lt)) < rem);
            unsigned bs = __ballot_sync(FULL, sel);
            unsigned bo = __ballot_sync(FULL, valid && !sel);
            if (sel)        cidx[cb + __popc(bs & lt)] = (short)d;
            else if (valid) oidx[ob + __popc(bo & lt)] = (short)d;
            eqb += __popc(be); cb += __popc(bs); ob += __popc(bo);
        }
    }
    __syncthreads();

    const float sigma = sigma_p ? *sigma_p : 0.05f;
    const float* xb = x + b * DD;

    // per-lane static gather indices + x values
    const int dC0 = cidx[lane];
    const int dC1 = cidx[32 + lane];
    const float xC0 = xb[dC0];
    const float xC1 = xb[dC1];
    int dO[5]; float xO[5];
#pragma unroll
    for (int j = 0; j < 5; ++j) {
        int p = j * 32 + lane;
        if (p < NO) { dO[j] = oidx[p]; xO[j] = xb[dO[j]]; }
        else        { dO[j] = 0;       xO[j] = -INFINITY; }
    }

    const float* nbase = noise + (size_t)b * NN * DD;

    // ---- software-pipelined main loop: prefetch next sample's 7 gathers ----
    float cc0, cc1, co0, co1, co2, co3, co4;
    {
        const float* row = nbase + (size_t)((warp < NN) ? warp : (NN - 1)) * DD;
        cc0 = row[dC0]; cc1 = row[dC1];
        co0 = row[dO[0]]; co1 = row[dO[1]]; co2 = row[dO[2]];
        co3 = row[dO[3]]; co4 = row[dO[4]];
    }

    for (int n = warp; n < NN; n += NWARPS) {
        // prefetch next (clamped — value unused on last iteration)
        int n2 = n + NWARPS;
        const float* row2 = nbase + (size_t)((n2 < NN) ? n2 : (NN - 1)) * DD;
        float pc0 = row2[dC0], pc1 = row2[dC1];
        float po0 = row2[dO[0]], po1 = row2[dO[1]], po2 = row2[dO[2]];
        float po3 = row2[dO[3]], po4 = row2[dO[4]];

        // candidate keys + non-candidate max for current sample
        unsigned k0 = f2key(fmaf(sigma, cc0, xC0));
        unsigned k1 = f2key(fmaf(sigma, cc1, xC1));
        float mo = fmaf(sigma, co0, xO[0]);
        mo = fmaxf(mo, fmaf(sigma, co1, xO[1]));
        mo = fmaxf(mo, fmaf(sigma, co2, xO[2]));
        mo = fmaxf(mo, fmaf(sigma, co3, xO[3]));
        mo = fmaxf(mo, fmaf(sigma, co4, xO[4]));
        unsigned moK = __reduce_max_sync(FULL, f2key(mo));

        // common-prefix skip
        unsigned A = __reduce_and_sync(FULL, k0 & k1);
        unsigned O = __reduce_or_sync(FULL, k0 | k1);
        unsigned xr = A ^ O;
        unsigned vT;
        if (xr == 0u) {
            vT = A;
        } else {
            int hb = 31 - __clz(xr);
            int sb = hb | 1;    // odd start -> clean 2-bit rounds down to bit 0
            unsigned prefix = (sb >= 31) ? 0u : ((A >> (sb + 1)) << (sb + 1));
            // 2-bit radix rounds: 3 thresholds per round, counts packed in one REDUX
            for (int bb = sb; bb >= 1; bb -= 2) {
                unsigned t1 = prefix | (1u << (bb - 1));
                unsigned t2 = prefix | (2u << (bb - 1));
                unsigned t3 = prefix | (3u << (bb - 1));
                unsigned pc = (unsigned)((k0 >= t1) + (k1 >= t1))
                            + ((unsigned)((k0 >= t2) + (k1 >= t2)) << 8)
                            + ((unsigned)((k0 >= t3) + (k1 >= t3)) << 16);
                pc = __reduce_add_sync(FULL, pc);
                int c1 = pc & 255, c2 = (pc >> 8) & 255, c3 = (int)(pc >> 16);
                if      (c3 >= KK) { prefix = t3; if (c3 == KK) break; }
                else if (c2 >= KK) { prefix = t2; if (c2 == KK) break; }
                else if (c1 >= KK) { prefix = t1; if (c1 == KK) break; }
            }
            vT = prefix;
        }

        if (moK >= vT) {
            // a non-candidate might enter top-48 (or tie): exact full path
            const float* row = nbase + (size_t)n * DD;
            fallback_select(row, xb, sigma, acc, lane, lt);
        } else {
            int cgt = __reduce_add_sync(FULL, (int)(k0 > vT) + (int)(k1 > vT));
            int rem = KK - cgt;

            // scatter (list is ascending-d, slot0 then slot1 = ascending rank order)
            bool gt = k0 > vT, eq = (k0 == vT);
            unsigned be = __ballot_sync(FULL, eq);
            bool sel = gt || (eq && (__popc(be & lt)) < rem);
            unsigned bs = __ballot_sync(FULL, sel);
            if (sel) atomicAdd(&acc[(__popc(bs & lt)) * DD + dC0], 1);
            int eqb = __popc(be), selb = __popc(bs);

            gt = k1 > vT; eq = (k1 == vT);
            be = __ballot_sync(FULL, eq);
            sel = gt || (eq && (eqb + __popc(be & lt)) < rem);
            bs = __ballot_sync(FULL, sel);
            if (sel) atomicAdd(&acc[(selb + __popc(bs & lt)) * DD + dC1], 1);
        }

        // rotate prefetched values in
        cc0 = pc0; cc1 = pc1;
        co0 = po0; co1 = po1; co2 = po2; co3 = po3; co4 = po4;
    }

    __syncthreads();

    const float inv = 1.0f / (float)NN;
    float* ob = out + (size_t)b * KK * DD;
    for (int i = tid; i < KK * DD; i += THREADS)
        ob[i] = (float)acc[i] * inv;
}

extern "C" void kernel_launch(void* const* d_in, const int* in_sizes, int n_in,
                              void* d_out, int out_size)
{
    const float* x     = nullptr;
    const float* noise = nullptr;
    const float* sigma = nullptr;
    for (int i = 0; i < n_in; ++i) {
        if      (in_sizes[i] == BB * DD)      x     = (const float*)d_in[i];
        else if (in_sizes[i] == BB * NN * DD) noise = (const float*)d_in[i];
        else if (in_sizes[i] == 1)            sigma = (const float*)d_in[i];
    }
    ptk_kernel<<<BB, THREADS>>>(x, noise, sigma, (float*)d_out);
}

// round 9
// speedup vs baseline: 1.8746x; 1.8746x over previous
#include <cuda_runtime.h>
#include <cstdint>
#include <math.h>

#define BB 128
#define NN 1000
#define DD 196
#define KK 48
#define NC 64            // candidate columns (top-NC of x per batch row)
#define NO (DD - NC)     // 132 other columns
#define NWARPS 32
#define THREADS (NWARPS * 32)
#define NPROBE 16
#define PLO 40           // probe ladder covers x-candidate ranks 40..55 (0-indexed)

__device__ __forceinline__ unsigned f2key(float v) {
    unsigned u = __float_as_uint(v);
    return u ^ ((unsigned)((int)u >> 31) | 0x80000000u);
}

// Exact full-width fallback: top-KK of all 196 perturbed values, d-ascending ranks.
__device__ __noinline__ void fallback_select(const float* __restrict__ row,
                                             const float* __restrict__ xb,
                                             float sigma, int* acc,
                                             int lane, unsigned lt)
{
    const unsigned FULL = 0xffffffffu;
    unsigned key[7];
#pragma unroll
    for (int j = 0; j < 7; ++j) {
        int d = j * 32 + lane;
        key[j] = (d < DD) ? f2key(fmaf(sigma, row[d], xb[d])) : 0u;
    }
    unsigned prefix = 0;
    for (int bit = 31; bit >= 0; --bit) {
        unsigned t = prefix | (1u << bit);
        int c = 0;
#pragma unroll
        for (int j = 0; j < 7; ++j) c += (key[j] >= t);
        c = __reduce_add_sync(FULL, c);
        if (c >= KK) { prefix = t; if (c == KK) break; }
    }
    int cgt = 0;
#pragma unroll
    for (int j = 0; j < 7; ++j) cgt += (key[j] > prefix);
    cgt = __reduce_add_sync(FULL, cgt);
    int rem = KK - cgt;
    int selb = 0, eqb = 0;
#pragma unroll
    for (int j = 0; j < 7; ++j) {
        bool gt = key[j] > prefix;
        bool eq = (key[j] == prefix);
        unsigned be = __ballot_sync(FULL, eq);
        bool sel = gt || (eq && (eqb + __popc(be & lt)) < rem);
        unsigned bs = __ballot_sync(FULL, sel);
        if (sel) atomicAdd(&acc[(selb + __popc(bs & lt)) * DD + (j * 32 + lane)], 1);
        eqb += __popc(be);
        selb += __popc(bs);
    }
}

__global__ __launch_bounds__(THREADS, 1)
void ptk_kernel(const float* __restrict__ x,
                const float* __restrict__ noise,
                const float* __restrict__ sigma_p,
                float* __restrict__ out)
{
    __shared__ int acc[KK * DD];        // 37632 B
    __shared__ short cidx[NC];          // candidate column ids, ascending d
    __shared__ short oidx[NO];          // other column ids, ascending d
    __shared__ unsigned probeT[NPROBE]; // x-candidate keys at ranks PLO..PLO+15 (descending)

    const int b = blockIdx.x, tid = threadIdx.x, lane = tid & 31, warp = tid >> 5;
    const unsigned lt = (1u << lane) - 1u;
    const unsigned FULL = 0xffffffffu;

    for (int i = tid; i < KK * DD; i += THREADS) acc[i] = 0;

    // ---- per-b precompute (warp 0): exact top-NC columns of x + probe ladder ----
    if (warp == 0) {
        unsigned key[7];
#pragma unroll
        for (int j = 0; j < 7; ++j) {
            int d = j * 32 + lane;
            key[j] = (d < DD) ? f2key(x[b * DD + d]) : 0u;
        }
        unsigned prefix = 0;
        for (int bit = 31; bit >= 0; --bit) {
            unsigned t = prefix | (1u << bit);
            int c = 0;
#pragma unroll
            for (int j = 0; j < 7; ++j) c += (key[j] >= t);
            c = __reduce_add_sync(FULL, c);
            if (c >= NC) { prefix = t; if (c == NC) break; }
        }
        int cgt = 0;
#pragma unroll
        for (int j = 0; j < 7; ++j) cgt += (key[j] > prefix);
        cgt = __reduce_add_sync(FULL, cgt);
        int rem = NC - cgt;
        int cb = 0, ob = 0, eqb = 0;
#pragma unroll
        for (int j = 0; j < 7; ++j) {
            int d = j * 32 + lane;
            bool valid = d < DD;
            bool gt = key[j] > prefix;
            bool eq = valid && (key[j] == prefix);
            unsigned be = __ballot_sync(FULL, eq);
            bool sel = gt || (eq && (eqb + __popc(be & lt)) < rem);
            unsigned bs = __ballot_sync(FULL, sel);
            unsigned bo = __ballot_sync(FULL, valid && !sel);
            if (sel)        cidx[cb + __popc(bs & lt)] = (short)d;
            else if (valid) oidx[ob + __popc(bo & lt)] = (short)d;
            eqb += __popc(be); cb += __popc(bs); ob += __popc(bo);
        }
        __syncwarp();

        // probe ladder: rank the 64 candidate x-keys (desc key, asc slot tiebreak)
        const float* xbp = x + b * DD;
        unsigned a0 = f2key(xbp[cidx[lane]]);       // slot = lane
        unsigned a1 = f2key(xbp[cidx[32 + lane]]);  // slot = lane + 32
        int r0 = 0, r1 = 0;
        for (int src = 0; src < 32; ++src) {
            unsigned b0 = __shfl_sync(FULL, a0, src);
            unsigned b1 = __shfl_sync(FULL, a1, src);
            r0 += (b0 > a0) + (b1 > a0) + ((b0 == a0) && (src < lane));
            r1 += (b0 > a1) + (b1 > a1) + (b0 == a1) + ((b1 == a1) && (src < lane));
        }
        if (r0 >= PLO && r0 < PLO + NPROBE) probeT[r0 - PLO] = a0;
        if (r1 >= PLO && r1 < PLO + NPROBE) probeT[r1 - PLO] = a1;
    }
    __syncthreads();

    const float sigma = sigma_p ? *sigma_p : 0.05f;
    const float* xb = x + b * DD;

    // per-lane static gather indices + x values
    const int dC0 = cidx[lane];
    const int dC1 = cidx[32 + lane];
    const float xC0 = xb[dC0];
    const float xC1 = xb[dC1];
    int dO[5]; float xO[5];
#pragma unroll
    for (int j = 0; j < 5; ++j) {
        int p = j * 32 + lane;
        if (p < NO) { dO[j] = oidx[p]; xO[j] = xb[dO[j]]; }
        else        { dO[j] = 0;       xO[j] = -INFINITY; }
    }

    const float* nbase = noise + (size_t)b * NN * DD;
    const volatile unsigned* vpt = probeT;   // volatile: re-read each iter, no 16-reg hoist

    for (int n = warp; n < NN; n += NWARPS) {
        const float* row = nbase + (size_t)n * DD;

        // candidate keys + non-candidate max
        unsigned k0 = f2key(fmaf(sigma, row[dC0], xC0));
        unsigned k1 = f2key(fmaf(sigma, row[dC1], xC1));
        float mo = fmaf(sigma, row[dO[0]], xO[0]);
        mo = fmaxf(mo, fmaf(sigma, row[dO[1]], xO[1]));
        mo = fmaxf(mo, fmaf(sigma, row[dO[2]], xO[2]));
        mo = fmaxf(mo, fmaf(sigma, row[dO[3]], xO[3]));
        mo = fmaxf(mo, fmaf(sigma, row[dO[4]], xO[4]));
        unsigned moK = __reduce_max_sync(FULL, f2key(mo));

        // ---- probe ladder: 16 counts via 4 independent packed REDUXes ----
        unsigned pcq[4];
#pragma unroll
        for (int q = 0; q < 4; ++q) {
            unsigned p = 0;
#pragma unroll
            for (int s = 0; s < 4; ++s) {
                unsigned T = vpt[4 * q + s];
                p += (unsigned)((k0 >= T) + (k1 >= T)) << (8 * s);
            }
            pcq[q] = __reduce_add_sync(FULL, p);
        }

        // first probe with count >= 48 (counts nondecreasing along ladder)
        int ii = -1; unsigned cval = 0;
#pragma unroll
        for (int q = 0; q < 4; ++q) {
            unsigned m = __vcmpgeu4(pcq[q], 0x30303030u);
            if (ii < 0 && m != 0u) {
                int by = (__ffs(m) - 1) >> 3;
                ii = 4 * q + by;
                cval = (pcq[q] >> (8 * by)) & 255u;
            }
        }

        unsigned vT = 0u;
        bool have = false, needfull = false;
        if (ii < 0)              needfull = true;          // ladder too high
        else if (cval == KK)   { vT = probeT[ii]; have = true; }
        else if (ii == 0)        needfull = true;          // jumped past 48 before ladder
        else {
            // bracket: c(lo) > 48, c(hi) < 48, lo < hi in key space
            unsigned lo = probeT[ii], hi = probeT[ii - 1];
            for (int it = 0; it < 8; ++it) {
                unsigned gap = hi - lo;
                if (gap <= 1u) break;
                unsigned qq = gap >> 2;
                unsigned m1, m2, m3;
                if (gap >= 4u) { m1 = lo + qq; m2 = lo + 2 * qq; m3 = hi - qq; }
                else           { m1 = lo + (gap >> 1); m2 = m1; m3 = m1; }
                unsigned p = (unsigned)((k0 >= m1) + (k1 >= m1))
                           | ((unsigned)((k0 >= m2) + (k1 >= m2)) << 8)
                           | ((unsigned)((k0 >= m3) + (k1 >= m3)) << 16);
                p = __reduce_add_sync(FULL, p);
                int c1 = p & 255, c2 = (p >> 8) & 255, c3 = (int)((p >> 16) & 255);
                if      (c3 == KK) { vT = m3; have = true; break; }
                else if (c2 == KK) { vT = m2; have = true; break; }
                else if (c1 == KK) { vT = m1; have = true; break; }
                else if (c3 > KK)  lo = m3;
                else if (c2 > KK)  { lo = m2; hi = m3; }
                else if (c1 > KK)  { lo = m1; hi = m2; }
                else               hi = m1;
            }
            if (!have) needfull = true;
        }

        if (needfull) {
            // R4's exact 1-bit radix (rare path): common-prefix skip + descent
            unsigned A = __reduce_and_sync(FULL, k0 & k1);
            unsigned O = __reduce_or_sync(FULL, k0 | k1);
            unsigned xr = A ^ O;
            if (xr == 0u) {
                vT = A;
            } else {
                int hb = 31 - __clz(xr);
                unsigned prefix = (hb < 31) ? ((A >> (hb + 1)) << (hb + 1)) : 0u;
                for (int bit = hb; bit >= 0; --bit) {
                    unsigned t = prefix | (1u << bit);
                    int c = (int)(k0 >= t) + (int)(k1 >= t);
                    c = __reduce_add_sync(FULL, c);
                    if (c >= KK) { prefix = t; if (c == KK) break; }
                }
                vT = prefix;
            }
        }

        if (moK >= vT) {
            // a non-candidate might enter top-48 (or tie): exact full path
            fallback_select(row, xb, sigma, acc, lane, lt);
        } else {
            int cgt = __reduce_add_sync(FULL, (int)(k0 > vT) + (int)(k1 > vT));
            int rem = KK - cgt;

            // scatter (ascending-d list; slot0 then slot1 = ascending rank order)
            bool gt = k0 > vT, eq = (k0 == vT);
            unsigned be = __ballot_sync(FULL, eq);
            bool sel = gt || (eq && (__popc(be & lt)) < rem);
            unsigned bs = __ballot_sync(FULL, sel);
            if (sel) atomicAdd(&acc[(__popc(bs & lt)) * DD + dC0], 1);
            int eqb = __popc(be), selb = __popc(bs);

            gt = k1 > vT; eq = (k1 == vT);
            be = __ballot_sync(FULL, eq);
            sel = gt || (eq && (eqb + __popc(be & lt)) < rem);
            bs = __ballot_sync(FULL, sel);
            if (sel) atomicAdd(&acc[(selb + __popc(bs & lt)) * DD + dC1], 1);
        }
    }

    __syncthreads();

    const float inv = 1.0f / (float)NN;
    float* ob = out + (size_t)b * KK * DD;
    for (int i = tid; i < KK * DD; i += THREADS)
        ob[i] = (float)acc[i] * inv;
}

extern "C" void kernel_launch(void* const* d_in, const int* in_sizes, int n_in,
                              void* d_out, int out_size)
{
    const float* x     = nullptr;
    const float* noise = nullptr;
    const float* sigma = nullptr;
    for (int i = 0; i < n_in; ++i) {
        if      (in_sizes[i] == BB * DD)      x     = (const float*)d_in[i];
        else if (in_sizes[i] == BB * NN * DD) noise = (const float*)d_in[i];
        else if (in_sizes[i] == 1)            sigma = (const float*)d_in[i];
    }
    ptk_kernel<<<BB, THREADS>>>(x, noise, sigma, (float*)d_out);
}

// round 11
// speedup vs baseline: 2.0409x; 1.0887x over previous
#include <cuda_runtime.h>
#include <cstdint>
#include <math.h>

#define BB 128
#define NN 1000
#define DD 196
#define KK 48
#define NC 64            // candidate columns (top-NC of x per batch row)
#define NO (DD - NC)     // 132 other columns
#define NWARPS 32
#define THREADS (NWARPS * 32)
#define NPROBE 16
#define PLO 40           // probe ladder covers x-candidate ranks 40..55 (0-indexed)

__device__ __forceinline__ unsigned f2key(float v) {
    unsigned u = __float_as_uint(v);
    return u ^ ((unsigned)((int)u >> 31) | 0x80000000u);
}

// Exact full-width fallback: top-KK of all 196 perturbed values, d-ascending ranks.
__device__ __noinline__ void fallback_select(const float* __restrict__ row,
                                             const float* __restrict__ xb,
                                             float sigma, int* acc,
                                             int lane, unsigned lt)
{
    const unsigned FULL = 0xffffffffu;
    unsigned key[7];
#pragma unroll
    for (int j = 0; j < 7; ++j) {
        int d = j * 32 + lane;
        key[j] = (d < DD) ? f2key(fmaf(sigma, row[d], xb[d])) : 0u;
    }
    unsigned prefix = 0;
    for (int bit = 31; bit >= 0; --bit) {
        unsigned t = prefix | (1u << bit);
        int c = 0;
#pragma unroll
        for (int j = 0; j < 7; ++j) c += (key[j] >= t);
        c = __reduce_add_sync(FULL, c);
        if (c >= KK) { prefix = t; if (c == KK) break; }
    }
    int cgt = 0;
#pragma unroll
    for (int j = 0; j < 7; ++j) cgt += (key[j] > prefix);
    cgt = __reduce_add_sync(FULL, cgt);
    int rem = KK - cgt;
    int selb = 0, eqb = 0;
#pragma unroll
    for (int j = 0; j < 7; ++j) {
        bool gt = key[j] > prefix;
        bool eq = (key[j] == prefix);
        unsigned be = __ballot_sync(FULL, eq);
        bool sel = gt || (eq && (eqb + __popc(be & lt)) < rem);
        unsigned bs = __ballot_sync(FULL, sel);
        if (sel) atomicAdd(&acc[(selb + __popc(bs & lt)) * DD + (j * 32 + lane)], 1);
        eqb += __popc(be);
        selb += __popc(bs);
    }
}

__global__ __launch_bounds__(THREADS, 1)
void ptk_kernel(const float* __restrict__ x,
                const float* __restrict__ noise,
                const float* __restrict__ sigma_p,
                float* __restrict__ out)
{
    __shared__ int acc[KK * DD];        // 37632 B
    __shared__ short cidx[NC];          // candidate column ids, ascending d
    __shared__ short oidx[NO];          // other column ids, ascending d
    __shared__ __align__(16) unsigned probeT[NPROBE]; // x-keys at ranks PLO..PLO+15

    const int b = blockIdx.x, tid = threadIdx.x, lane = tid & 31, warp = tid >> 5;
    const unsigned lt = (1u << lane) - 1u;
    const unsigned FULL = 0xffffffffu;

    for (int i = tid; i < KK * DD; i += THREADS) acc[i] = 0;

    // ---- per-b precompute (warp 0): exact top-NC columns of x + probe ladder ----
    if (warp == 0) {
        unsigned key[7];
#pragma unroll
        for (int j = 0; j < 7; ++j) {
            int d = j * 32 + lane;
            key[j] = (d < DD) ? f2key(x[b * DD + d]) : 0u;
        }
        unsigned prefix = 0;
        for (int bit = 31; bit >= 0; --bit) {
            unsigned t = prefix | (1u << bit);
            int c = 0;
#pragma unroll
            for (int j = 0; j < 7; ++j) c += (key[j] >= t);
            c = __reduce_add_sync(FULL, c);
            if (c >= NC) { prefix = t; if (c == NC) break; }
        }
        int cgt = 0;
#pragma unroll
        for (int j = 0; j < 7; ++j) cgt += (key[j] > prefix);
        cgt = __reduce_add_sync(FULL, cgt);
        int rem = NC - cgt;
        int cb = 0, ob = 0, eqb = 0;
#pragma unroll
        for (int j = 0; j < 7; ++j) {
            int d = j * 32 + lane;
            bool valid = d < DD;
            bool gt = key[j] > prefix;
            bool eq = valid && (key[j] == prefix);
            unsigned be = __ballot_sync(FULL, eq);
            bool sel = gt || (eq && (eqb + __popc(be & lt)) < rem);
            unsigned bs = __ballot_sync(FULL, sel);
            unsigned bo = __ballot_sync(FULL, valid && !sel);
            if (sel)        cidx[cb + __popc(bs & lt)] = (short)d;
            else if (valid) oidx[ob + __popc(bo & lt)] = (short)d;
            eqb += __popc(be); cb += __popc(bs); ob += __popc(bo);
        }
        __syncwarp();

        // probe ladder: rank the 64 candidate x-keys (desc key, asc slot tiebreak)
        const float* xbp = x + b * DD;
        unsigned a0 = f2key(xbp[cidx[lane]]);       // slot = lane
        unsigned a1 = f2key(xbp[cidx[32 + lane]]);  // slot = lane + 32
        int r0 = 0, r1 = 0;
        for (int src = 0; src < 32; ++src) {
            unsigned b0 = __shfl_sync(FULL, a0, src);
            unsigned b1 = __shfl_sync(FULL, a1, src);
            r0 += (b0 > a0) + (b1 > a0) + ((b0 == a0) && (src < lane));
            r1 += (b0 > a1) + (b1 > a1) + (b0 == a1) + ((b1 == a1) && (src < lane));
        }
        if (r0 >= PLO && r0 < PLO + NPROBE) probeT[r0 - PLO] = a0;
        if (r1 >= PLO && r1 < PLO + NPROBE) probeT[r1 - PLO] = a1;
    }
    __syncthreads();

    const float sigma = sigma_p ? *sigma_p : 0.05f;
    const float* xb = x + b * DD;

    // per-lane static gather indices + x values
    const int dC0 = cidx[lane];
    const int dC1 = cidx[32 + lane];
    const float xC0 = xb[dC0];
    const float xC1 = xb[dC1];
    int dO[5]; float xO[5];
#pragma unroll
    for (int j = 0; j < 5; ++j) {
        int p = j * 32 + lane;
        if (p < NO) { dO[j] = oidx[p]; xO[j] = xb[dO[j]]; }
        else        { dO[j] = 0;       xO[j] = -INFINITY; }
    }

    const float* nbase = noise + (size_t)b * NN * DD;
    const uint4* pt4 = (const uint4*)probeT;

    for (int n = warp; n < NN; n += NWARPS) {
        const float* row = nbase + (size_t)n * DD;

        // candidate keys + non-candidate max (tree)
        unsigned k0 = f2key(fmaf(sigma, row[dC0], xC0));
        unsigned k1 = f2key(fmaf(sigma, row[dC1], xC1));
        float f0 = fmaf(sigma, row[dO[0]], xO[0]);
        float f1 = fmaf(sigma, row[dO[1]], xO[1]);
        float f2 = fmaf(sigma, row[dO[2]], xO[2]);
        float f3 = fmaf(sigma, row[dO[3]], xO[3]);
        float f4 = fmaf(sigma, row[dO[4]], xO[4]);
        float mo = fmaxf(fmaxf(fmaxf(f0, f1), fmaxf(f2, f3)), f4);

        // ---- 16 probe counts via 4 independent packed REDUXes (+ moK overlapped) ----
        uint4 q0 = pt4[0], q1 = pt4[1], q2 = pt4[2], q3 = pt4[3];
        unsigned p0 = (unsigned)((k0 >= q0.x) + (k1 >= q0.x))
                    | ((unsigned)((k0 >= q0.y) + (k1 >= q0.y)) << 8)
                    | ((unsigned)((k0 >= q0.z) + (k1 >= q0.z)) << 16)
                    | ((unsigned)((k0 >= q0.w) + (k1 >= q0.w)) << 24);
        unsigned p1 = (unsigned)((k0 >= q1.x) + (k1 >= q1.x))
                    | ((unsigned)((k0 >= q1.y) + (k1 >= q1.y)) << 8)
                    | ((unsigned)((k0 >= q1.z) + (k1 >= q1.z)) << 16)
                    | ((unsigned)((k0 >= q1.w) + (k1 >= q1.w)) << 24);
        unsigned p2 = (unsigned)((k0 >= q2.x) + (k1 >= q2.x))
                    | ((unsigned)((k0 >= q2.y) + (k1 >= q2.y)) << 8)
                    | ((unsigned)((k0 >= q2.z) + (k1 >= q2.z)) << 16)
                    | ((unsigned)((k0 >= q2.w) + (k1 >= q2.w)) << 24);
        unsigned p3 = (unsigned)((k0 >= q3.x) + (k1 >= q3.x))
                    | ((unsigned)((k0 >= q3.y) + (k1 >= q3.y)) << 8)
                    | ((unsigned)((k0 >= q3.z) + (k1 >= q3.z)) << 16)
                    | ((unsigned)((k0 >= q3.w) + (k1 >= q3.w)) << 24);
        unsigned moK = f2key(mo);
        p0 = __reduce_add_sync(FULL, p0);
        p1 = __reduce_add_sync(FULL, p1);
        p2 = __reduce_add_sync(FULL, p2);
        p3 = __reduce_add_sync(FULL, p3);
        moK = __reduce_max_sync(FULL, moK);

        // first probe with count >= 48 (counts nondecreasing along ladder)
        unsigned pcq[4] = { p0, p1, p2, p3 };
        int ii = -1; unsigned cval = 0;
#pragma unroll
        for (int q = 0; q < 4; ++q) {
            unsigned m = __vcmpgeu4(pcq[q], 0x30303030u);
            if (ii < 0 && m != 0u) {
                int by = (__ffs(m) - 1) >> 3;
                ii = 4 * q + by;
                cval = (pcq[q] >> (8 * by)) & 255u;
            }
        }

        unsigned vT = 0u;
        bool have = false, needfull = false;
        if (ii < 0)              needfull = true;          // ladder too high
        else if (cval == KK)   { vT = probeT[ii]; have = true; }
        else if (ii == 0)        needfull = true;          // jumped past 48 before ladder
        else {
            // bracket: c(lo) > 48, c(hi) < 48, lo < hi in key space
            unsigned lo = probeT[ii], hi = probeT[ii - 1];
            for (int it = 0; it < 8; ++it) {
                unsigned gap = hi - lo;
                if (gap <= 1u) break;
                unsigned qq = gap >> 2;
                unsigned m1, m2, m3;
                if (gap >= 4u) { m1 = lo + qq; m2 = lo + 2 * qq; m3 = hi - qq; }
                else           { m1 = lo + (gap >> 1); m2 = m1; m3 = m1; }
                unsigned p = (unsigned)((k0 >= m1) + (k1 >= m1))
                           | ((unsigned)((k0 >= m2) + (k1 >= m2)) << 8)
                           | ((unsigned)((k0 >= m3) + (k1 >= m3)) << 16);
                p = __reduce_add_sync(FULL, p);
                int c1 = p & 255, c2 = (p >> 8) & 255, c3 = (int)((p >> 16) & 255);
                if      (c3 == KK) { vT = m3; have = true; break; }
                else if (c2 == KK) { vT = m2; have = true; break; }
                else if (c1 == KK) { vT = m1; have = true; break; }
                else if (c3 > KK)  lo = m3;
                else if (c2 > KK)  { lo = m2; hi = m3; }
                else if (c1 > KK)  { lo = m1; hi = m2; }
                else               hi = m1;
            }
            if (!have) needfull = true;
        }

        if (needfull) {
            // Exact 1-bit radix + full tie-break scatter (rare path)
            unsigned A = __reduce_and_sync(FULL, k0 & k1);
            unsigned O = __reduce_or_sync(FULL, k0 | k1);
            unsigned xr = A ^ O;
            if (xr == 0u) {
                vT = A;
            } else {
                int hb = 31 - __clz(xr);
                unsigned prefix = (hb < 31) ? ((A >> (hb + 1)) << (hb + 1)) : 0u;
                for (int bit = hb; bit >= 0; --bit) {
                    unsigned t = prefix | (1u << bit);
                    int c = (int)(k0 >= t) + (int)(k1 >= t);
                    c = __reduce_add_sync(FULL, c);
                    if (c >= KK) { prefix = t; if (c == KK) break; }
                }
                vT = prefix;
            }

            if (moK >= vT) {
                fallback_select(row, xb, sigma, acc, lane, lt);
            } else {
                int cgt = __reduce_add_sync(FULL, (int)(k0 > vT) + (int)(k1 > vT));
                int rem = KK - cgt;
                bool gt = k0 > vT, eq = (k0 == vT);
                unsigned be = __ballot_sync(FULL, eq);
                bool sel = gt || (eq && (__popc(be & lt)) < rem);
                unsigned bs = __ballot_sync(FULL, sel);
                if (sel) atomicAdd(&acc[(__popc(bs & lt)) * DD + dC0], 1);
                int eqb = __popc(be), selb = __popc(bs);

                gt = k1 > vT; eq = (k1 == vT);
                be = __ballot_sync(FULL, eq);
                sel = gt || (eq && (eqb + __popc(be & lt)) < rem);
                bs = __ballot_sync(FULL, sel);
                if (sel) atomicAdd(&acc[(selb + __popc(bs & lt)) * DD + dC1], 1);
            }
        } else {
            // HIT path: c(vT) == 48 exactly -> selected set is {k >= vT}, no ties
            if (moK >= vT) {
                fallback_select(row, xb, sigma, acc, lane, lt);
            } else {
                bool s0 = (k0 >= vT);
                bool s1 = (k1 >= vT);
                unsigned bs0 = __ballot_sync(FULL, s0);
                unsigned bs1 = __ballot_sync(FULL, s1);
                if (s0) atomicAdd(&acc[(__popc(bs0 & lt)) * DD + dC0], 1);
                if (s1) atomicAdd(&acc[(__popc(bs0) + __popc(bs1 & lt)) * DD + dC1], 1);
            }
        }
    }

    __syncthreads();

    const float inv = 1.0f / (float)NN;
    float* ob = out + (size_t)b * KK * DD;
    for (int i = tid; i < KK * DD; i += THREADS)
        ob[i] = (float)acc[i] * inv;
}

extern "C" void kernel_launch(void* const* d_in, const int* in_sizes, int n_in,
                              void* d_out, int out_size)
{
    const float* x     = nullptr;
    const float* noise = nullptr;
    const float* sigma = nullptr;
    for (int i = 0; i < n_in; ++i) {
        if      (in_sizes[i] == BB * DD)      x     = (const float*)d_in[i];
        else if (in_sizes[i] == BB * NN * DD) noise = (const float*)d_in[i];
        else if (in_sizes[i] == 1)            sigma = (const float*)d_in[i];
    }
    ptk_kernel<<<BB, THREADS>>>(x, noise, sigma, (float*)d_out);
}

// round 13
// speedup vs baseline: 2.4987x; 1.2243x over previous
#include <cuda_runtime.h>
#include <cstdint>
#include <math.h>

#define BB 128
#define NN 1000
#define DD 196
#define KK 48
#define NC 64            // candidate columns (top-NC of x per batch row)
#define NO (DD - NC)     // 132 other columns
#define NWARPS 32
#define THREADS (NWARPS * 32)
#define NPROBE 16
#define PLO 40           // probe ladder covers x-candidate ranks 40..55 (0-indexed)

__device__ __forceinline__ unsigned f2key(float v) {
    unsigned u = __float_as_uint(v);
    return u ^ ((unsigned)((int)u >> 31) | 0x80000000u);
}

// Exact full-width fallback: top-KK of all 196 perturbed values, d-ascending ranks.
__device__ __noinline__ void fallback_select(const float* __restrict__ row,
                                             const float* __restrict__ xb,
                                             float sigma, int* acc,
                                             int lane, unsigned lt)
{
    const unsigned FULL = 0xffffffffu;
    unsigned key[7];
#pragma unroll
    for (int j = 0; j < 7; ++j) {
        int d = j * 32 + lane;
        key[j] = (d < DD) ? f2key(fmaf(sigma, row[d], xb[d])) : 0u;
    }
    unsigned prefix = 0;
    for (int bit = 31; bit >= 0; --bit) {
        unsigned t = prefix | (1u << bit);
        int c = 0;
#pragma unroll
        for (int j = 0; j < 7; ++j) c += (key[j] >= t);
        c = __reduce_add_sync(FULL, c);
        if (c >= KK) { prefix = t; if (c == KK) break; }
    }
    int cgt = 0;
#pragma unroll
    for (int j = 0; j < 7; ++j) cgt += (key[j] > prefix);
    cgt = __reduce_add_sync(FULL, cgt);
    int rem = KK - cgt;
    int selb = 0, eqb = 0;
#pragma unroll
    for (int j = 0; j < 7; ++j) {
        bool gt = key[j] > prefix;
        bool eq = (key[j] == prefix);
        unsigned be = __ballot_sync(FULL, eq);
        bool sel = gt || (eq && (eqb + __popc(be & lt)) < rem);
        unsigned bs = __ballot_sync(FULL, sel);
        if (sel) atomicAdd(&acc[(selb + __popc(bs & lt)) * DD + (j * 32 + lane)], 1);
        eqb += __popc(be);
        selb += __popc(bs);
    }
}

__global__ __launch_bounds__(THREADS, 1)
void ptk_kernel(const float* __restrict__ x,
                const float* __restrict__ noise,
                const float* __restrict__ sigma_p,
                float* __restrict__ out)
{
    __shared__ int acc[KK * DD];        // 37632 B
    __shared__ short cidx[NC];          // candidate column ids, ascending d
    __shared__ short oidx[NO];          // other column ids, ascending d
    __shared__ __align__(16) unsigned probeT[NPROBE]; // x-keys at ranks PLO..PLO+15

    const int b = blockIdx.x, tid = threadIdx.x, lane = tid & 31, warp = tid >> 5;
    const unsigned lt = (1u << lane) - 1u;
    const unsigned FULL = 0xffffffffu;

    for (int i = tid; i < KK * DD; i += THREADS) acc[i] = 0;

    // ---- per-b precompute (warp 0): exact top-NC columns of x + probe ladder ----
    if (warp == 0) {
        unsigned key[7];
#pragma unroll
        for (int j = 0; j < 7; ++j) {
            int d = j * 32 + lane;
            key[j] = (d < DD) ? f2key(x[b * DD + d]) : 0u;
        }
        unsigned prefix = 0;
        for (int bit = 31; bit >= 0; --bit) {
            unsigned t = prefix | (1u << bit);
            int c = 0;
#pragma unroll
            for (int j = 0; j < 7; ++j) c += (key[j] >= t);
            c = __reduce_add_sync(FULL, c);
            if (c >= NC) { prefix = t; if (c == NC) break; }
        }
        int cgt = 0;
#pragma unroll
        for (int j = 0; j < 7; ++j) cgt += (key[j] > prefix);
        cgt = __reduce_add_sync(FULL, cgt);
        int rem = NC - cgt;
        int cb = 0, ob = 0, eqb = 0;
#pragma unroll
        for (int j = 0; j < 7; ++j) {
            int d = j * 32 + lane;
            bool valid = d < DD;
            bool gt = key[j] > prefix;
            bool eq = valid && (key[j] == prefix);
            unsigned be = __ballot_sync(FULL, eq);
            bool sel = gt || (eq && (eqb + __popc(be & lt)) < rem);
            unsigned bs = __ballot_sync(FULL, sel);
            unsigned bo = __ballot_sync(FULL, valid && !sel);
            if (sel)        cidx[cb + __popc(bs & lt)] = (short)d;
            else if (valid) oidx[ob + __popc(bo & lt)] = (short)d;
            eqb += __popc(be); cb += __popc(bs); ob += __popc(bo);
        }
        __syncwarp();

        // probe ladder: rank the 64 candidate x-keys (desc key, asc slot tiebreak)
        const float* xbp = x + b * DD;
        unsigned a0 = f2key(xbp[cidx[lane]]);       // slot = lane
        unsigned a1 = f2key(xbp[cidx[32 + lane]]);  // slot = lane + 32
        int r0 = 0, r1 = 0;
        for (int src = 0; src < 32; ++src) {
            unsigned b0 = __shfl_sync(FULL, a0, src);
            unsigned b1 = __shfl_sync(FULL, a1, src);
            r0 += (b0 > a0) + (b1 > a0) + ((b0 == a0) && (src < lane));
            r1 += (b0 > a1) + (b1 > a1) + (b0 == a1) + ((b1 == a1) && (src < lane));
        }
        if (r0 >= PLO && r0 < PLO + NPROBE) probeT[r0 - PLO] = a0;
        if (r1 >= PLO && r1 < PLO + NPROBE) probeT[r1 - PLO] = a1;
    }
    __syncthreads();

    const float sigma = sigma_p ? *sigma_p : 0.05f;
    const float* xb = x + b * DD;

    // per-lane static gather indices + x values
    const int dC0 = cidx[lane];
    const int dC1 = cidx[32 + lane];
    const float xC0 = xb[dC0];
    const float xC1 = xb[dC1];
    int dO[5]; float xO[5];
#pragma unroll
    for (int j = 0; j < 5; ++j) {
        int p = j * 32 + lane;
        if (p < NO) { dO[j] = oidx[p]; xO[j] = xb[dO[j]]; }
        else        { dO[j] = 0;       xO[j] = -INFINITY; }
    }

    // level-1 probes hoisted into registers: ladder indices 0,4,8,12 (ranks 40,44,48,52)
    const unsigned fl0 = probeT[0], fl1 = probeT[4], fl2 = probeT[8], fl3 = probeT[12];

    const float* nbase = noise + (size_t)b * NN * DD;

    for (int n = warp; n < NN; n += NWARPS) {
        const float* row = nbase + (size_t)n * DD;

        // candidate keys + non-candidate max (tree)
        unsigned k0 = f2key(fmaf(sigma, row[dC0], xC0));
        unsigned k1 = f2key(fmaf(sigma, row[dC1], xC1));
        float f0 = fmaf(sigma, row[dO[0]], xO[0]);
        float f1 = fmaf(sigma, row[dO[1]], xO[1]);
        float f2 = fmaf(sigma, row[dO[2]], xO[2]);
        float f3 = fmaf(sigma, row[dO[3]], xO[3]);
        float f4 = fmaf(sigma, row[dO[4]], xO[4]);
        float mo = fmaxf(fmaxf(fmaxf(f0, f1), fmaxf(f2, f3)), f4);

        // ---- level-1: 4 probe counts in one packed REDUX (+ moK overlapped) ----
        unsigned pc = (unsigned)((k0 >= fl0) + (k1 >= fl0))
                    | ((unsigned)((k0 >= fl1) + (k1 >= fl1)) << 8)
                    | ((unsigned)((k0 >= fl2) + (k1 >= fl2)) << 16)
                    | ((unsigned)((k0 >= fl3) + (k1 >= fl3)) << 24);
        unsigned moK = f2key(mo);
        pc  = __reduce_add_sync(FULL, pc);
        moK = __reduce_max_sync(FULL, moK);

        unsigned vT = 0u;
        bool have = false, needfull = false;

        unsigned e = __vcmpeq4(pc, 0x30303030u);   // bytes with count == 48
        unsigned g = __vcmpgeu4(pc, 0x30303030u);  // bytes with count >= 48

        if (e != 0u) {
            // exact hit at a level-1 probe
            int by = (__ffs(e) - 1) >> 3;
            vT = probeT[4 * by];
            have = true;
        } else if (g != 0u && (g & 0xffu) != 0u) {
            needfull = true;                       // c(rank40) > 48: above ladder
        } else {
            // bracket: ladder index p has c<48; upper end (p+4) has c>48 iff g!=0
            int p; bool haveUpper;
            if (g != 0u) { int by = (__ffs(g) - 1) >> 3; p = 4 * (by - 1); haveUpper = true; }
            else         { p = 12; haveUpper = false; }

            // ---- level-2: 3 interior probes in one packed REDUX ----
            unsigned T1 = probeT[p + 1], T2 = probeT[p + 2], T3 = probeT[p + 3];
            unsigned sc = (unsigned)((k0 >= T1) + (k1 >= T1))
                        | ((unsigned)((k0 >= T2) + (k1 >= T2)) << 8)
                        | ((unsigned)((k0 >= T3) + (k1 >= T3)) << 16);
            sc = __reduce_add_sync(FULL, sc);
            int c1 = sc & 255, c2 = (sc >> 8) & 255, c3 = (int)((sc >> 16) & 255);

            unsigned lo = 0u, hi = 0u; bool bisect = false;
            if      (c1 == KK) { vT = T1; have = true; }
            else if (c1 >  KK) { lo = T1; hi = probeT[p]; bisect = true; }
            else if (c2 == KK) { vT = T2; have = true; }
            else if (c2 >  KK) { lo = T2; hi = T1; bisect = true; }
            else if (c3 == KK) { vT = T3; have = true; }
            else if (c3 >  KK) { lo = T3; hi = T2; bisect = true; }
            else if (haveUpper) { lo = probeT[p + 4]; hi = T3; bisect = true; } // c(p+4)>48
            else needfull = true;                  // below ladder bottom

            if (bisect) {
                // c(lo) > 48, c(hi) < 48, lo < hi in key space
                for (int it = 0; it < 8; ++it) {
                    unsigned gap = hi - lo;
                    if (gap <= 1u) break;
                    unsigned qq = gap >> 2;
                    unsigned m1, m2, m3;
                    if (gap >= 4u) { m1 = lo + qq; m2 = lo + 2 * qq; m3 = hi - qq; }
                    else           { m1 = lo + (gap >> 1); m2 = m1; m3 = m1; }
                    unsigned pp = (unsigned)((k0 >= m1) + (k1 >= m1))
                                | ((unsigned)((k0 >= m2) + (k1 >= m2)) << 8)
                                | ((unsigned)((k0 >= m3) + (k1 >= m3)) << 16);
                    pp = __reduce_add_sync(FULL, pp);
                    int b1 = pp & 255, b2 = (pp >> 8) & 255, b3 = (int)((pp >> 16) & 255);
                    if      (b3 == KK) { vT = m3; have = true; break; }
                    else if (b2 == KK) { vT = m2; have = true; break; }
                    else if (b1 == KK) { vT = m1; have = true; break; }
                    else if (b3 > KK)  lo = m3;
                    else if (b2 > KK)  { lo = m2; hi = m3; }
                    else if (b1 > KK)  { lo = m1; hi = m2; }
                    else               hi = m1;
                }
                if (!have) needfull = true;
            }
        }

        if (needfull) {
            // Exact 1-bit radix + full tie-break scatter (rare path)
            unsigned A = __reduce_and_sync(FULL, k0 & k1);
            unsigned O = __reduce_or_sync(FULL, k0 | k1);
            unsigned xr = A ^ O;
            if (xr == 0u) {
                vT = A;
            } else {
                int hb = 31 - __clz(xr);
                unsigned prefix = (hb < 31) ? ((A >> (hb + 1)) << (hb + 1)) : 0u;
                for (int bit = hb; bit >= 0; --bit) {
                    unsigned t = prefix | (1u << bit);
                    int c = (int)(k0 >= t) + (int)(k1 >= t);
                    c = __reduce_add_sync(FULL, c);
                    if (c >= KK) { prefix = t; if (c == KK) break; }
                }
                vT = prefix;
            }

            if (moK >= vT) {
                fallback_select(row, xb, sigma, acc, lane, lt);
            } else {
                int cgt = __reduce_add_sync(FULL, (int)(k0 > vT) + (int)(k1 > vT));
                int rem = KK - cgt;
                bool gt = k0 > vT, eq = (k0 == vT);
                unsigned be = __ballot_sync(FULL, eq);
                bool sel = gt || (eq && (__popc(be & lt)) < rem);
                unsigned bs = __ballot_sync(FULL, sel);
                if (sel) atomicAdd(&acc[(__popc(bs & lt)) * DD + dC0], 1);
                int eqb = __popc(be), selb = __popc(bs);

                gt = k1 > vT; eq = (k1 == vT);
                be = __ballot_sync(FULL, eq);
                sel = gt || (eq && (eqb + __popc(be & lt)) < rem);
                bs = __ballot_sync(FULL, sel);
                if (sel) atomicAdd(&acc[(selb + __popc(bs & lt)) * DD + dC1], 1);
            }
        } else {
            // HIT path: c(vT) == 48 exactly -> selected set is {k >= vT}, no ties
            if (moK >= vT) {
                fallback_select(row, xb, sigma, acc, lane, lt);
            } else {
                bool s0 = (k0 >= vT);
                bool s1 = (k1 >= vT);
                unsigned bs0 = __ballot_sync(FULL, s0);
                unsigned bs1 = __ballot_sync(FULL, s1);
                if (s0) atomicAdd(&acc[(__popc(bs0 & lt)) * DD + dC0], 1);
                if (s1) atomicAdd(&acc[(__popc(bs0) + __popc(bs1 & lt)) * DD + dC1], 1);
            }
        }
    }

    __syncthreads();

    const float inv = 1.0f / (float)NN;
    float* ob = out + (size_t)b * KK * DD;
    for (int i = tid; i < KK * DD; i += THREADS)
        ob[i] = (float)acc[i] * inv;
}

extern "C" void kernel_launch(void* const* d_in, const int* in_sizes, int n_in,
                              void* d_out, int out_size)
{
    const float* x     = nullptr;
    const float* noise = nullptr;
    const float* sigma = nullptr;
    for (int i = 0; i < n_in; ++i) {
        if      (in_sizes[i] == BB * DD)      x     = (const float*)d_in[i];
        else if (in_sizes[i] == BB * NN * DD) noise = (const float*)d_in[i];
        else if (in_sizes[i] == 1)            sigma = (const float*)d_in[i];
    }
    ptk_kernel<<<BB, THREADS>>>(x, noise, sigma, (float*)d_out);
}

// round 15
// speedup vs baseline: 2.5101x; 1.0046x over previous
#include <cuda_runtime.h>
#include <cstdint>
#include <math.h>

#define BB 128
#define NN 1000
#define DD 196
#define KK 48
#define NC 64            // candidate columns (top-NC of x per batch row)
#define NO (DD - NC)     // 132 other columns
#define NWARPS 32
#define THREADS (NWARPS * 32)
#define NPROBE 16
#define PLO 40           // probe ladder covers x-candidate ranks 40..55 (0-indexed)

__device__ __forceinline__ unsigned f2key(float v) {
    unsigned u = __float_as_uint(v);
    return u ^ ((unsigned)((int)u >> 31) | 0x80000000u);
}

// Exact full-width fallback: top-KK of all 196 perturbed values, d-ascending ranks.
__device__ __noinline__ void fallback_select(const float* __restrict__ row,
                                             const float* __restrict__ xb,
                                             float sigma, int* acc,
                                             int lane, unsigned lt)
{
    const unsigned FULL = 0xffffffffu;
    unsigned key[7];
#pragma unroll
    for (int j = 0; j < 7; ++j) {
        int d = j * 32 + lane;
        key[j] = (d < DD) ? f2key(fmaf(sigma, row[d], xb[d])) : 0u;
    }
    unsigned prefix = 0;
    for (int bit = 31; bit >= 0; --bit) {
        unsigned t = prefix | (1u << bit);
        int c = 0;
#pragma unroll
        for (int j = 0; j < 7; ++j) c += (key[j] >= t);
        c = __reduce_add_sync(FULL, c);
        if (c >= KK) { prefix = t; if (c == KK) break; }
    }
    int cgt = 0;
#pragma unroll
    for (int j = 0; j < 7; ++j) cgt += (key[j] > prefix);
    cgt = __reduce_add_sync(FULL, cgt);
    int rem = KK - cgt;
    int selb = 0, eqb = 0;
#pragma unroll
    for (int j = 0; j < 7; ++j) {
        bool gt = key[j] > prefix;
        bool eq = (key[j] == prefix);
        unsigned be = __ballot_sync(FULL, eq);
        bool sel = gt || (eq && (eqb + __popc(be & lt)) < rem);
        unsigned bs = __ballot_sync(FULL, sel);
        if (sel) atomicAdd(&acc[(selb + __popc(bs & lt)) * DD + (j * 32 + lane)], 1);
        eqb += __popc(be);
        selb += __popc(bs);
    }
}

// Post-REDUX tail: ladder scan -> (hit | level2 | bisect | full radix) -> scatter.
// pc/moK are already warp-reduced. Exactness identical to R13.
__device__ __forceinline__ void resolve_scatter(
    unsigned k0, unsigned k1, unsigned pc, unsigned moK,
    const float* __restrict__ row, const float* __restrict__ xb, float sigma,
    int* acc, const unsigned* probeT,
    int dC0, int dC1, int lane, unsigned lt)
{
    const unsigned FULL = 0xffffffffu;
    unsigned vT = 0u;
    bool have = false, needfull = false;

    unsigned e = __vcmpeq4(pc, 0x30303030u);   // bytes with count == 48
    unsigned g = __vcmpgeu4(pc, 0x30303030u);  // bytes with count >= 48

    if (e != 0u) {
        int by = (__ffs(e) - 1) >> 3;
        vT = probeT[4 * by];
        have = true;
    } else if (g != 0u && (g & 0xffu) != 0u) {
        needfull = true;                       // c(rank40) > 48: above ladder
    } else {
        int p; bool haveUpper;
        if (g != 0u) { int by = (__ffs(g) - 1) >> 3; p = 4 * (by - 1); haveUpper = true; }
        else         { p = 12; haveUpper = false; }

        // level-2: 3 interior probes in one packed REDUX
        unsigned T1 = probeT[p + 1], T2 = probeT[p + 2], T3 = probeT[p + 3];
        unsigned sc = (unsigned)((k0 >= T1) + (k1 >= T1))
                    | ((unsigned)((k0 >= T2) + (k1 >= T2)) << 8)
                    | ((unsigned)((k0 >= T3) + (k1 >= T3)) << 16);
        sc = __reduce_add_sync(FULL, sc);
        int c1 = sc & 255, c2 = (sc >> 8) & 255, c3 = (int)((sc >> 16) & 255);

        unsigned lo = 0u, hi = 0u; bool bisect = false;
        if      (c1 == KK) { vT = T1; have = true; }
        else if (c1 >  KK) { lo = T1; hi = probeT[p]; bisect = true; }
        else if (c2 == KK) { vT = T2; have = true; }
        else if (c2 >  KK) { lo = T2; hi = T1; bisect = true; }
        else if (c3 == KK) { vT = T3; have = true; }
        else if (c3 >  KK) { lo = T3; hi = T2; bisect = true; }
        else if (haveUpper) { lo = probeT[p + 4]; hi = T3; bisect = true; }
        else needfull = true;                  // below ladder bottom

        if (bisect) {
            // c(lo) > 48, c(hi) < 48, lo < hi in key space
            for (int it = 0; it < 8; ++it) {
                unsigned gap = hi - lo;
                if (gap <= 1u) break;
                unsigned qq = gap >> 2;
                unsigned m1, m2, m3;
                if (gap >= 4u) { m1 = lo + qq; m2 = lo + 2 * qq; m3 = hi - qq; }
                else           { m1 = lo + (gap >> 1); m2 = m1; m3 = m1; }
                unsigned pp = (unsigned)((k0 >= m1) + (k1 >= m1))
                            | ((unsigned)((k0 >= m2) + (k1 >= m2)) << 8)
                            | ((unsigned)((k0 >= m3) + (k1 >= m3)) << 16);
                pp = __reduce_add_sync(FULL, pp);
                int b1 = pp & 255, b2 = (pp >> 8) & 255, b3 = (int)((pp >> 16) & 255);
                if      (b3 == KK) { vT = m3; have = true; break; }
                else if (b2 == KK) { vT = m2; have = true; break; }
                else if (b1 == KK) { vT = m1; have = true; break; }
                else if (b3 > KK)  lo = m3;
                else if (b2 > KK)  { lo = m2; hi = m3; }
                else if (b1 > KK)  { lo = m1; hi = m2; }
                else               hi = m1;
            }
            if (!have) needfull = true;
        }
    }

    if (needfull) {
        // Exact 1-bit radix + full tie-break scatter (rare path)
        unsigned A = __reduce_and_sync(FULL, k0 & k1);
        unsigned O = __reduce_or_sync(FULL, k0 | k1);
        unsigned xr = A ^ O;
        if (xr == 0u) {
            vT = A;
        } else {
            int hb = 31 - __clz(xr);
            unsigned prefix = (hb < 31) ? ((A >> (hb + 1)) << (hb + 1)) : 0u;
            for (int bit = hb; bit >= 0; --bit) {
                unsigned t = prefix | (1u << bit);
                int c = (int)(k0 >= t) + (int)(k1 >= t);
                c = __reduce_add_sync(FULL, c);
                if (c >= KK) { prefix = t; if (c == KK) break; }
            }
            vT = prefix;
        }

        if (moK >= vT) {
            fallback_select(row, xb, sigma, acc, lane, lt);
        } else {
            int cgt = __reduce_add_sync(FULL, (int)(k0 > vT) + (int)(k1 > vT));
            int rem = KK - cgt;
            bool gt = k0 > vT, eq = (k0 == vT);
            unsigned be = __ballot_sync(FULL, eq);
            bool sel = gt || (eq && (__popc(be & lt)) < rem);
            unsigned bs = __ballot_sync(FULL, sel);
            if (sel) atomicAdd(&acc[(__popc(bs & lt)) * DD + dC0], 1);
            int eqb = __popc(be), selb = __popc(bs);

            gt = k1 > vT; eq = (k1 == vT);
            be = __ballot_sync(FULL, eq);
            sel = gt || (eq && (eqb + __popc(be & lt)) < rem);
            bs = __ballot_sync(FULL, sel);
            if (sel) atomicAdd(&acc[(selb + __popc(bs & lt)) * DD + dC1], 1);
        }
    } else {
        // HIT path: c(vT) == 48 exactly -> selected set is {k >= vT}, no ties
        if (moK >= vT) {
            fallback_select(row, xb, sigma, acc, lane, lt);
        } else {
            bool s0 = (k0 >= vT);
            bool s1 = (k1 >= vT);
            unsigned bs0 = __ballot_sync(FULL, s0);
            unsigned bs1 = __ballot_sync(FULL, s1);
            if (s0) atomicAdd(&acc[(__popc(bs0 & lt)) * DD + dC0], 1);
            if (s1) atomicAdd(&acc[(__popc(bs0) + __popc(bs1 & lt)) * DD + dC1], 1);
        }
    }
}

__global__ __launch_bounds__(THREADS, 1)
void ptk_kernel(const float* __restrict__ x,
                const float* __restrict__ noise,
                const float* __restrict__ sigma_p,
                float* __restrict__ out)
{
    __shared__ int acc[KK * DD];        // 37632 B
    __shared__ short cidx[NC];          // candidate column ids, ascending d
    __shared__ short oidx[NO];          // other column ids, ascending d
    __shared__ __align__(16) unsigned probeT[NPROBE]; // x-keys at ranks PLO..PLO+15

    const int b = blockIdx.x, tid = threadIdx.x, lane = tid & 31, warp = tid >> 5;
    const unsigned lt = (1u << lane) - 1u;
    const unsigned FULL = 0xffffffffu;

    for (int i = tid; i < KK * DD; i += THREADS) acc[i] = 0;

    // ---- per-b precompute (warp 0): exact top-NC columns of x + probe ladder ----
    if (warp == 0) {
        unsigned key[7];
#pragma unroll
        for (int j = 0; j < 7; ++j) {
            int d = j * 32 + lane;
            key[j] = (d < DD) ? f2key(x[b * DD + d]) : 0u;
        }
        unsigned prefix = 0;
        for (int bit = 31; bit >= 0; --bit) {
            unsigned t = prefix | (1u << bit);
            int c = 0;
#pragma unroll
            for (int j = 0; j < 7; ++j) c += (key[j] >= t);
            c = __reduce_add_sync(FULL, c);
            if (c >= NC) { prefix = t; if (c == NC) break; }
        }
        int cgt = 0;
#pragma unroll
        for (int j = 0; j < 7; ++j) cgt += (key[j] > prefix);
        cgt = __reduce_add_sync(FULL, cgt);
        int rem = NC - cgt;
        int cb = 0, ob = 0, eqb = 0;
#pragma unroll
        for (int j = 0; j < 7; ++j) {
            int d = j * 32 + lane;
            bool valid = d < DD;
            bool gt = key[j] > prefix;
            bool eq = valid && (key[j] == prefix);
            unsigned be = __ballot_sync(FULL, eq);
            bool sel = gt || (eq && (eqb + __popc(be & lt)) < rem);
            unsigned bs = __ballot_sync(FULL, sel);
            unsigned bo = __ballot_sync(FULL, valid && !sel);
            if (sel)        cidx[cb + __popc(bs & lt)] = (short)d;
            else if (valid) oidx[ob + __popc(bo & lt)] = (short)d;
            eqb += __popc(be); cb += __popc(bs); ob += __popc(bo);
        }
        __syncwarp();

        // probe ladder: rank the 64 candidate x-keys (desc key, asc slot tiebreak)
        const float* xbp = x + b * DD;
        unsigned a0 = f2key(xbp[cidx[lane]]);       // slot = lane
        unsigned a1 = f2key(xbp[cidx[32 + lane]]);  // slot = lane + 32
        int r0 = 0, r1 = 0;
        for (int src = 0; src < 32; ++src) {
            unsigned b0 = __shfl_sync(FULL, a0, src);
            unsigned b1 = __shfl_sync(FULL, a1, src);
            r0 += (b0 > a0) + (b1 > a0) + ((b0 == a0) && (src < lane));
            r1 += (b0 > a1) + (b1 > a1) + (b0 == a1) + ((b1 == a1) && (src < lane));
        }
        if (r0 >= PLO && r0 < PLO + NPROBE) probeT[r0 - PLO] = a0;
        if (r1 >= PLO && r1 < PLO + NPROBE) probeT[r1 - PLO] = a1;
    }
    __syncthreads();

    const float sigma = sigma_p ? *sigma_p : 0.05f;
    const float* xb = x + b * DD;

    // per-lane static gather indices + x values
    const int dC0 = cidx[lane];
    const int dC1 = cidx[32 + lane];
    const float xC0 = xb[dC0];
    const float xC1 = xb[dC1];
    int dO[5]; float xO[5];
#pragma unroll
    for (int j = 0; j < 5; ++j) {
        int p = j * 32 + lane;
        if (p < NO) { dO[j] = oidx[p]; xO[j] = xb[dO[j]]; }
        else        { dO[j] = 0;       xO[j] = -INFINITY; }
    }

    // level-1 probes hoisted into registers: ladder indices 0,4,8,12 (ranks 40,44,48,52)
    const unsigned fl0 = probeT[0], fl1 = probeT[4], fl2 = probeT[8], fl3 = probeT[12];

    const float* nbase = noise + (size_t)b * NN * DD;

    int n = warp;
    // ---- pairwise-pipelined main loop: 2 samples per iteration ----
    for (; n + NWARPS < NN; n += 2 * NWARPS) {
        const float* rowA = nbase + (size_t)n * DD;
        const float* rowB = nbase + (size_t)(n + NWARPS) * DD;

        // issue all 14 loads up front (one memory-latency exposure per pair)
        float ac0 = rowA[dC0], ac1 = rowA[dC1];
        float ao0 = rowA[dO[0]], ao1 = rowA[dO[1]], ao2 = rowA[dO[2]];
        float ao3 = rowA[dO[3]], ao4 = rowA[dO[4]];
        float bc0 = rowB[dC0], bc1 = rowB[dC1];
        float bo0 = rowB[dO[0]], bo1 = rowB[dO[1]], bo2 = rowB[dO[2]];
        float bo3 = rowB[dO[3]], bo4 = rowB[dO[4]];

        // keys + packed level-1 counts for A
        unsigned kA0 = f2key(fmaf(sigma, ac0, xC0));
        unsigned kA1 = f2key(fmaf(sigma, ac1, xC1));
        float moA = fmaxf(fmaxf(fmaxf(fmaf(sigma, ao0, xO[0]), fmaf(sigma, ao1, xO[1])),
                                fmaxf(fmaf(sigma, ao2, xO[2]), fmaf(sigma, ao3, xO[3]))),
                          fmaf(sigma, ao4, xO[4]));
        unsigned pcA = (unsigned)((kA0 >= fl0) + (kA1 >= fl0))
                     | ((unsigned)((kA0 >= fl1) + (kA1 >= fl1)) << 8)
                     | ((unsigned)((kA0 >= fl2) + (kA1 >= fl2)) << 16)
                     | ((unsigned)((kA0 >= fl3) + (kA1 >= fl3)) << 24);
        unsigned moKA = f2key(moA);

        // keys + packed level-1 counts for B (B's floats die here)
        unsigned kB0 = f2key(fmaf(sigma, bc0, xC0));
        unsigned kB1 = f2key(fmaf(sigma, bc1, xC1));
        float moB = fmaxf(fmaxf(fmaxf(fmaf(sigma, bo0, xO[0]), fmaf(sigma, bo1, xO[1])),
                                fmaxf(fmaf(sigma, bo2, xO[2]), fmaf(sigma, bo3, xO[3]))),
                          fmaf(sigma, bo4, xO[4]));
        unsigned pcB = (unsigned)((kB0 >= fl0) + (kB1 >= fl0))
                     | ((unsigned)((kB0 >= fl1) + (kB1 >= fl1)) << 8)
                     | ((unsigned)((kB0 >= fl2) + (kB1 >= fl2)) << 16)
                     | ((unsigned)((kB0 >= fl3) + (kB1 >= fl3)) << 24);
        unsigned moKB = f2key(moB);

        // four independent reductions back-to-back (latencies overlap)
        pcA  = __reduce_add_sync(FULL, pcA);
        moKA = __reduce_max_sync(FULL, moKA);
        pcB  = __reduce_add_sync(FULL, pcB);
        moKB = __reduce_max_sync(FULL, moKB);

        resolve_scatter(kA0, kA1, pcA, moKA, rowA, xb, sigma, acc, probeT,
                        dC0, dC1, lane, lt);
        resolve_scatter(kB0, kB1, pcB, moKB, rowB, xb, sigma, acc, probeT,
                        dC0, dC1, lane, lt);
    }
    // tail: at most one remaining sample
    if (n < NN) {
        const float* row = nbase + (size_t)n * DD;
        unsigned k0 = f2key(fmaf(sigma, row[dC0], xC0));
        unsigned k1 = f2key(fmaf(sigma, row[dC1], xC1));
        float mo = fmaxf(fmaxf(fmaxf(fmaf(sigma, row[dO[0]], xO[0]),
                                     fmaf(sigma, row[dO[1]], xO[1])),
                               fmaxf(fmaf(sigma, row[dO[2]], xO[2]),
                                     fmaf(sigma, row[dO[3]], xO[3]))),
                         fmaf(sigma, row[dO[4]], xO[4]));
        unsigned pc = (unsigned)((k0 >= fl0) + (k1 >= fl0))
                    | ((unsigned)((k0 >= fl1) + (k1 >= fl1)) << 8)
                    | ((unsigned)((k0 >= fl2) + (k1 >= fl2)) << 16)
                    | ((unsigned)((k0 >= fl3) + (k1 >= fl3)) << 24);
        unsigned moK = f2key(mo);
        pc  = __reduce_add_sync(FULL, pc);
        moK = __reduce_max_sync(FULL, moK);
        resolve_scatter(k0, k1, pc, moK, row, xb, sigma, acc, probeT,
                        dC0, dC1, lane, lt);
    }

    __syncthreads();

    const float inv = 1.0f / (float)NN;
    float* ob = out + (size_t)b * KK * DD;
    for (int i = tid; i < KK * DD; i += THREADS)
        ob[i] = (float)acc[i] * inv;
}

extern "C" void kernel_launch(void* const* d_in, const int* in_sizes, int n_in,
                              void* d_out, int out_size)
{
    const float* x     = nullptr;
    const float* noise = nullptr;
    const float* sigma = nullptr;
    for (int i = 0; i < n_in; ++i) {
        if      (in_sizes[i] == BB * DD)      x     = (const float*)d_in[i];
        else if (in_sizes[i] == BB * NN * DD) noise = (const float*)d_in[i];
        else if (in_sizes[i] == 1)            sigma = (const float*)d_in[i];
    }
    ptk_kernel<<<BB, THREADS>>>(x, noise, sigma, (float*)d_out);
}